// round 17
// baseline (speedup 1.0000x reference)
#include <cuda_runtime.h>
#include <cuda_bf16.h>
#include <cstdint>

// Problem dims
#define BATCH 1024
#define TSTEPS 200
#define DDIM 128

#define THREADS 512
#define CLUSTER_SIZE 4
#define MT 32                     // batch rows per cluster

// SMEM layout (bytes)
#define SM_BHI 0                  // [128 n][512 B]
#define SM_BLO 65536
#define SM_H1A 131072             // L1's h1(t+1) copy: 16 KB (hi 8K + lo 8K); doubles as L1 red-buf
#define SM_H1C 147456             // L2's h1(t+1) copy: 16 KB
#define SM_H2  163840             // 16 KB; doubles as L2 red-buf
#define SM_X   180224             // 2 slots x 16 KB
#define SMEM_MAIN 212992

// device globals (no allocation allowed)
__device__ __nv_bfloat16 gx_hi[(size_t)BATCH*TSTEPS*DDIM];
__device__ __nv_bfloat16 gx_lo[(size_t)BATCH*TSTEPS*DDIM];
__device__ __nv_bfloat16 gh1[2][BATCH*256];  // [slot][row*256 + plane*128 + cell]
__device__ __nv_bfloat16 gh2[2][BATCH*256];

// ---------------- helpers ----------------
__device__ __forceinline__ uint32_t smem_u32(const void* p){
    uint32_t a;
    asm("{ .reg .u64 t; cvta.to.shared.u64 t, %1; cvt.u32.u64 %0, t; }" : "=r"(a) : "l"(p));
    return a;
}
__device__ __forceinline__ uint32_t cl_rank(){
    uint32_t r; asm("mov.u32 %0, %%cluster_ctarank;" : "=r"(r)); return r;
}
__device__ __forceinline__ void cl_arrive(){ asm volatile("barrier.cluster.arrive.aligned;" ::: "memory"); }
__device__ __forceinline__ void cl_wait(){ asm volatile("barrier.cluster.wait.aligned;" ::: "memory"); }
__device__ __forceinline__ void barn(int id){ asm volatile("bar.sync %0, 256;" :: "r"(id) : "memory"); }
__device__ __forceinline__ void cpa16(uint32_t dst, const void* src){
    asm volatile("cp.async.cg.shared.global [%0], [%1], 16;" :: "r"(dst), "l"(src));
}
__device__ __forceinline__ void cp_commit(){ asm volatile("cp.async.commit_group;" ::: "memory"); }
template<int N> __device__ __forceinline__ void cp_wait(){ asm volatile("cp.async.wait_group %0;" :: "n"(N) : "memory"); }

__device__ __forceinline__ void ldsm4(uint32_t& r0, uint32_t& r1, uint32_t& r2, uint32_t& r3, uint32_t addr){
    asm volatile("ldmatrix.sync.aligned.m8n8.x4.shared.b16 {%0,%1,%2,%3}, [%4];"
                 : "=r"(r0), "=r"(r1), "=r"(r2), "=r"(r3) : "r"(addr));
}
__device__ __forceinline__ void hmma(float* c, const uint32_t* a, uint32_t b0, uint32_t b1){
    asm volatile("mma.sync.aligned.m16n8k16.row.col.f32.bf16.bf16.f32 "
                 "{%0,%1,%2,%3}, {%4,%5,%6,%7}, {%8,%9}, {%0,%1,%2,%3};"
                 : "+f"(c[0]), "+f"(c[1]), "+f"(c[2]), "+f"(c[3])
                 : "r"(a[0]), "r"(a[1]), "r"(a[2]), "r"(a[3]), "r"(b0), "r"(b1));
}
__device__ __forceinline__ float fsig(float x){ return __fdividef(1.f, 1.f + __expf(-x)); }
__device__ __forceinline__ float ftanh_(float x){
    x = fminf(15.f, fmaxf(-15.f, x));
    float e = __expf(2.f * x);
    return __fdividef(e - 1.f, e + 1.f);
}
__device__ __forceinline__ void split1(float v, __nv_bfloat16& hi, __nv_bfloat16& lo){
    hi = __float2bfloat16(v);
    lo = __float2bfloat16(v - __bfloat162float(hi));
}
__device__ __forceinline__ void split4(float4 v, uint2& hi, uint2& lo){
    __nv_bfloat16 hx, hy, hz, hw, lx, ly, lz, lw;
    split1(v.x, hx, lx); split1(v.y, hy, ly); split1(v.z, hz, lz); split1(v.w, hw, lw);
    __nv_bfloat162 h01; h01.x = hx; h01.y = hy;
    __nv_bfloat162 h23; h23.x = hz; h23.y = hw;
    __nv_bfloat162 l01; l01.x = lx; l01.y = ly;
    __nv_bfloat162 l23; l23.x = lz; l23.y = lw;
    hi.x = *reinterpret_cast<uint32_t*>(&h01); hi.y = *reinterpret_cast<uint32_t*>(&h23);
    lo.x = *reinterpret_cast<uint32_t*>(&l01); lo.y = *reinterpret_cast<uint32_t*>(&l23);
}

// -------- pre-kernel: split x into bf16 hi/lo --------
__global__ void __launch_bounds__(256)
split_x_kernel(const float* __restrict__ x)
{
    int i = blockIdx.x * 256 + threadIdx.x;
    float4 v = reinterpret_cast<const float4*>(x)[i];
    uint2 hi, lo; split4(v, hi, lo);
    reinterpret_cast<uint2*>(gx_hi)[i] = hi;
    reinterpret_cast<uint2*>(gx_lo)[i] = lo;
}

extern __shared__ char smem[];

// -------- main persistent kernel: 16 warps, m32n32k64 tiles (k-split) --------
__global__ void __launch_bounds__(THREADS, 1) __cluster_dims__(CLUSTER_SIZE, 1, 1)
lstm_main_kernel(const float* __restrict__ W,
                 const float* __restrict__ U,
                 const float* __restrict__ bias,
                 float* __restrict__ out)
{
    const uint32_t sbase = smem_u32(smem);
    const int tid = threadIdx.x;
    const int wid = tid >> 5, lane = tid & 31;
    const uint32_t rank = cl_rank();
    const int m0 = (blockIdx.x >> 2) * MT;
    const int layer = wid >> 3;          // 0: warps 0-7 (layer1), 1: warps 8-15 (layer2)
    const int lw = wid & 7;              // warp within layer
    const int ws = lw & 3;               // n32 cell-slice (0..3)
    const int kh = lw >> 2;              // k-half (0..1); kh==0 owns epilogue
    const int ks0 = kh * 4;              // ks start for this k-half
    const int lt = tid & 255;            // index within layer group (256 threads)

    // ---- B build: n = gate*32 + cell_local, [128 n][512 B] swizzled (one-time)
    #pragma unroll
    for (int i = 0; i < 16; ++i){
        int tsk = tid + i * THREADS;
        int n = tsk >> 6, kq = tsk & 63, k = kq * 4;
        int gate = n >> 5, cell = n & 31;
        int col = gate * 128 + (int)rank * 32 + cell;
        float4 v;
        float* vv = reinterpret_cast<float*>(&v);
        #pragma unroll
        for (int j = 0; j < 4; ++j){
            int kk = k + j;
            vv[j] = (kk < 128) ? W[kk * 512 + col] : U[(kk - 128) * 512 + col];
        }
        uint2 hi, lo; split4(v, hi, lo);
        uint32_t so = n * 512 + ((((kq >> 1) ^ (n & 7)) << 4)) + ((kq & 1) << 3);
        *reinterpret_cast<uint2*>(smem + SM_BHI + so) = hi;
        *reinterpret_cast<uint2*>(smem + SM_BLO + so) = lo;
    }

    // ---- prefetch x(0) -> X slot0, x(1) -> X slot1 (all threads)
    #pragma unroll
    for (int slot = 0; slot < 2; ++slot){
        #pragma unroll
        for (int i = 0; i < 2; ++i){
            int idx = tid + i * THREADS;
            int pl = idx >> 9, r = (idx >> 4) & 31, u = idx & 15;
            const __nv_bfloat16* sp = (pl ? gx_lo : gx_hi)
                + ((size_t)(m0 + r) * TSTEPS + slot) * DDIM + u * 8;
            cpa16(sbase + SM_X + slot * 16384 + pl * 8192
                  + r * 256 + (((u ^ (r & 7)) << 4)), sp);
        }
        cp_commit();
    }

    // ---- per-warp coordinates: m32 x n32 x k64 tile
    const int a_row0 = lane & 15;
    const int a_row1 = a_row0 + 16;
    const uint32_t a0b = a_row0 * 256, a0x = (a_row0 & 7) << 4;
    const uint32_t a1b = a_row1 * 256, a1x = (a_row1 & 7) << 4;
    const uint32_t a_lk = (lane >> 4) << 4;
    const int n01 = ws * 8 + (lane & 7) + ((lane >> 4) << 5);
    const int n23 = n01 + 64;
    const uint32_t b01b = n01 * 512, b01x = (n01 & 7) << 4;
    const uint32_t b23b = n23 * 512, b23x = (n23 & 7) << 4;
    const uint32_t b_lk = ((lane >> 3) & 1) << 4;

    const int R0 = lane >> 2;                                 // local rows R0 + {0,8,16,24}
    const int gc = (int)rank * 32 + ws * 8 + (lane & 3) * 2;  // global cells gc, gc+1

    // ---- zero h2(0) own slice (layer2 kh0 warps)
    if (layer == 1 && kh == 0){
        __nv_bfloat162 z; z.x = __float2bfloat16(0.f); z.y = z.x;
        #pragma unroll
        for (int rr = 0; rr < 4; ++rr){
            int r = m0 + R0 + rr * 8;
            *reinterpret_cast<__nv_bfloat162*>(&gh2[0][r * 256 + gc]) = z;
            *reinterpret_cast<__nv_bfloat162*>(&gh2[0][r * 256 + 128 + gc]) = z;
        }
    }

    float bia[4][2];
    #pragma unroll
    for (int g = 0; g < 4; ++g){
        bia[g][0] = bias[g * 128 + gc];
        bia[g][1] = bias[g * 128 + gc + 1];
    }

    float cst[8];                 // c-state (kh0 warps only)
    #pragma unroll
    for (int j = 0; j < 8; ++j) cst[j] = 0.f;

    float acc[2][4][4];
    float* af = &acc[0][0][0];    // flat view (32 floats)

    // kh0 -> bias, kh1 -> zero (avoid double-bias after reduction)
    #define ACC_INIT()                                          \
        _Pragma("unroll")                                       \
        for (int mf = 0; mf < 2; ++mf)                          \
            _Pragma("unroll")                                   \
            for (int g = 0; g < 4; ++g){                        \
                float b0 = kh ? 0.f : bia[g][0];                \
                float b1 = kh ? 0.f : bia[g][1];                \
                acc[mf][g][0] = b0; acc[mf][g][1] = b1;         \
                acc[mf][g][2] = b0; acc[mf][g][3] = b1;         \
            }

    // k64 GEMM onto acc: A m32 from (AHI, ALO), B rows at +BOFS bytes, ks in [ks0, ks0+4)
    #define MMA4(AHI, ALO, BOFS)                                                       \
    {                                                                                  \
        _Pragma("unroll")                                                              \
        for (int kq_ = 0; kq_ < 4; ++kq_){                                             \
            int ks = ks0 + kq_;                                                        \
            uint32_t kbA = (uint32_t)(ks * 32) + a_lk;                                 \
            uint32_t kbB = (uint32_t)(ks * 32) + (uint32_t)(BOFS) + b_lk;              \
            uint32_t ah0[4], al0[4], ah1[4], al1[4], bh[8], bl[8];                     \
            ldsm4(ah0[0], ah0[1], ah0[2], ah0[3], (AHI) + a0b + (kbA ^ a0x));          \
            ldsm4(al0[0], al0[1], al0[2], al0[3], (ALO) + a0b + (kbA ^ a0x));          \
            ldsm4(ah1[0], ah1[1], ah1[2], ah1[3], (AHI) + a1b + (kbA ^ a1x));          \
            ldsm4(al1[0], al1[1], al1[2], al1[3], (ALO) + a1b + (kbA ^ a1x));          \
            ldsm4(bh[0], bh[1], bh[2], bh[3], sbase + SM_BHI + b01b + (kbB ^ b01x));   \
            ldsm4(bh[4], bh[5], bh[6], bh[7], sbase + SM_BHI + b23b + (kbB ^ b23x));   \
            ldsm4(bl[0], bl[1], bl[2], bl[3], sbase + SM_BLO + b01b + (kbB ^ b01x));   \
            ldsm4(bl[4], bl[5], bl[6], bl[7], sbase + SM_BLO + b23b + (kbB ^ b23x));   \
            _Pragma("unroll")                                                          \
            for (int g = 0; g < 4; ++g){                                               \
                hmma(acc[0][g], ah0, bh[g*2], bh[g*2+1]);                              \
                hmma(acc[0][g], ah0, bl[g*2], bl[g*2+1]);                              \
                hmma(acc[0][g], al0, bh[g*2], bh[g*2+1]);                              \
                hmma(acc[1][g], ah1, bh[g*2], bh[g*2+1]);                              \
                hmma(acc[1][g], ah1, bl[g*2], bl[g*2+1]);                              \
                hmma(acc[1][g], al1, bh[g*2], bh[g*2+1]);                              \
            }                                                                          \
        }                                                                              \
    }

    // k-half reduction through smem buffer BUF (16 KB region), bar id BID.
    // Pre-condition: a BID barrier separates prior reads of BUF from this store.
    #define KSPLIT_REDUCE(BUF, BID)                                                   \
    {                                                                                 \
        barn(BID);                                                                    \
        if (kh == 1){                                                                 \
            _Pragma("unroll")                                                         \
            for (int i = 0; i < 8; ++i)                                               \
                *reinterpret_cast<float4*>(smem + ((BUF) - sbase) + ws * 4096         \
                    + i * 512 + lane * 16) = *reinterpret_cast<float4*>(af + i * 4);  \
        }                                                                             \
        barn(BID);                                                                    \
        if (kh == 0){                                                                 \
            _Pragma("unroll")                                                         \
            for (int i = 0; i < 8; ++i){                                              \
                float4 p = *reinterpret_cast<const float4*>(smem + ((BUF) - sbase)    \
                    + ws * 4096 + i * 512 + lane * 16);                               \
                af[i*4+0] += p.x; af[i*4+1] += p.y;                                   \
                af[i*4+2] += p.z; af[i*4+3] += p.w;                                   \
            }                                                                         \
        }                                                                             \
    }

    #define EPILOGUE(HV)                                                              \
        _Pragma("unroll")                                                             \
        for (int mf = 0; mf < 2; ++mf)                                                \
            _Pragma("unroll")                                                         \
            for (int v = 0; v < 4; ++v){                                              \
                int j = mf * 4 + v;                                                   \
                float cn = fsig(acc[mf][1][v]) * cst[j]                               \
                         + fsig(acc[mf][0][v]) * ftanh_(acc[mf][2][v]);               \
                cst[j] = cn;                                                          \
                HV[j] = fsig(acc[mf][3][v]) * ftanh_(cn);                             \
            }

    // issue a 16KB h-buffer readback with this layer's 256 threads
    #define ISSUE_H(DSTBASE, SRC)                                                     \
    {                                                                                 \
        _Pragma("unroll")                                                             \
        for (int i = 0; i < 4; ++i){                                                  \
            int idx = lt + i * 256;                                                   \
            int pl = idx >> 9, r = (idx >> 4) & 31, u = idx & 15;                     \
            cpa16((DSTBASE) + pl * 8192 + r * 256 + (((u ^ (r & 7)) << 4)),           \
                  &(SRC)[(m0 + r) * 256 + pl * 128 + u * 8]);                         \
        }                                                                             \
    }

    const uint32_t H1A = sbase + SM_H1A, H1C = sbase + SM_H1C, H2b = sbase + SM_H2;

    // ---- prologue: layer1 computes h1(1) = E1(bias + x(0)·W); publish to gh1[1]
    cp_wait<0>();
    __syncthreads();
    if (layer == 0){
        ACC_INIT();
        MMA4(sbase + SM_X, sbase + SM_X + 8192, 0);
        KSPLIT_REDUCE(H1A, 1);
        if (kh == 0){
            float hv[8];
            EPILOGUE(hv);
            #pragma unroll
            for (int rr = 0; rr < 4; ++rr){
                int r = m0 + R0 + rr * 8;
                int j0 = (rr >> 1) * 4 + (rr & 1) * 2;
                __nv_bfloat162 hh, ll;
                split1(hv[j0], hh.x, ll.x);
                split1(hv[j0 + 1], hh.y, ll.y);
                *reinterpret_cast<__nv_bfloat162*>(&gh1[1][r * 256 + gc]) = hh;
                *reinterpret_cast<__nv_bfloat162*>(&gh1[1][r * 256 + 128 + gc]) = ll;
            }
        }
    }
    cl_arrive();     // B_{-1}: h1(1), h2(0) published

    for (int t = 0; t < TSTEPS; ++t){
        const int s = t & 1, ns = s ^ 1;
        const uint32_t Xrd = sbase + SM_X + ns * 16384;   // x(t+1)
        const uint32_t Xwr = sbase + SM_X + s * 16384;    // refill x(t+2)

        // ===== PRE-WAIT zone: barrier-independent work fills the skew window =====
        ACC_INIT();
        if (layer == 0){
            cp_wait<0>();                // all own prior groups retired (incl. x(t+1) refill)
            barn(1);                     // Xrd complete across all L1 threads
            if (t + 1 < TSTEPS){
                MMA4(Xrd, Xrd + 8192, 0);    // z1(t+1) += x(t+1)·W (own k-half)
            }
        }

        cl_wait();   // B_{t-1}: h1(t+1) [gh1[ns]] and h2(t) [gh2[s]] visible

        if (layer == 0){
            // ========= LAYER-1 post-wait =========
            ISSUE_H(H1A, gh1[ns]);           // h1(t+1) -> private copy
            cp_commit();
            if (t + 2 < TSTEPS){             // X refill x(t+2) -> slot s
                #pragma unroll
                for (int i = 0; i < 4; ++i){
                    int idx = lt + i * 256;
                    int pl = idx >> 9, r = (idx >> 4) & 31, u = idx & 15;
                    const __nv_bfloat16* sp = (pl ? gx_lo : gx_hi)
                        + ((size_t)(m0 + r) * TSTEPS + (t + 2)) * DDIM + u * 8;
                    cpa16(Xwr + pl * 8192 + r * 256 + (((u ^ (r & 7)) << 4)), sp);
                }
            }
            cp_commit();

            cp_wait<1>();                    // H1A done (mine); X refill still in flight
            barn(1);                         // H1A done (all L1 threads)
            MMA4(H1A, H1A + 8192, 256);      // z1(t+1) += h1(t+1)·U (own k-half)

            KSPLIT_REDUCE(H1A, 1);           // sum k-halves into kh0 acc

            if (kh == 0){
                float hv[8];
                EPILOGUE(hv);                // h1(t+2)
                #pragma unroll
                for (int rr = 0; rr < 4; ++rr){
                    int r = m0 + R0 + rr * 8;
                    int j0 = (rr >> 1) * 4 + (rr & 1) * 2;
                    __nv_bfloat162 hh, ll;
                    split1(hv[j0], hh.x, ll.x);
                    split1(hv[j0 + 1], hh.y, ll.y);
                    *reinterpret_cast<__nv_bfloat162*>(&gh1[s][r * 256 + gc]) = hh;
                    *reinterpret_cast<__nv_bfloat162*>(&gh1[s][r * 256 + 128 + gc]) = ll;
                }
            }
        } else {
            // ========= LAYER-2 post-wait =========
            ISSUE_H(H2b, gh2[s]);            // h2(t)
            cp_commit();
            ISSUE_H(H1C, gh1[ns]);           // h1(t+1) -> private copy
            cp_commit();

            cp_wait<1>();                    // H2b done (mine)
            barn(2);                         // H2b done (all L2 threads)
            MMA4(H2b, H2b + 8192, 256);      // z2 += h2(t)·U  (covers H1C)
            cp_wait<0>();                    // H1C done (mine)
            barn(2);
            MMA4(H1C, H1C + 8192, 0);        // z2 += h1(t+1)·W

            KSPLIT_REDUCE(H2b, 2);           // sum k-halves into kh0 acc

            if (kh == 0){
                // residual h1(t+1) from H1C (hi+lo reconstruct)
                float res[8];
                #pragma unroll
                for (int rr = 0; rr < 4; ++rr){
                    int rloc = R0 + rr * 8;
                    uint32_t ho = (uint32_t)(rloc * 256
                                + ((((uint32_t)(gc >> 3) ^ (uint32_t)(rloc & 7))) << 4)
                                + ((2 * gc) & 15));
                    __nv_bfloat162 hh = *reinterpret_cast<const __nv_bfloat162*>(smem + SM_H1C + ho);
                    __nv_bfloat162 ll = *reinterpret_cast<const __nv_bfloat162*>(smem + SM_H1C + 8192 + ho);
                    res[rr * 2 + 0] = __bfloat162float(hh.x) + __bfloat162float(ll.x);
                    res[rr * 2 + 1] = __bfloat162float(hh.y) + __bfloat162float(ll.y);
                }
                float hv[8];
                EPILOGUE(hv);
                #pragma unroll
                for (int rr = 0; rr < 4; ++rr){
                    int rloc = R0 + rr * 8;
                    int r = m0 + rloc;
                    int j0 = (rr >> 1) * 4 + (rr & 1) * 2;
                    float h0 = hv[j0] + res[rr * 2 + 0];      // + residual h1(t+1)
                    float h1v = hv[j0 + 1] + res[rr * 2 + 1];
                    __nv_bfloat162 hh, ll;
                    split1(h0, hh.x, ll.x);
                    split1(h1v, hh.y, ll.y);
                    *reinterpret_cast<__nv_bfloat162*>(&gh2[ns][r * 256 + gc]) = hh;
                    *reinterpret_cast<__nv_bfloat162*>(&gh2[ns][r * 256 + 128 + gc]) = ll;
                    float2 ov; ov.x = h0; ov.y = h1v;
                    *reinterpret_cast<float2*>(&out[((size_t)r * TSTEPS + t) * DDIM + gc]) = ov;
                }
            }
        }

        cl_arrive();     // B_t: h1(t+2) + h2(t+1) published
    }
    cl_wait();           // consume final arrive

    #undef ISSUE_H
    #undef EPILOGUE
    #undef KSPLIT_REDUCE
    #undef MMA4
    #undef ACC_INIT
}

extern "C" void kernel_launch(void* const* d_in, const int* in_sizes, int n_in,
                              void* d_out, int out_size)
{
    const float* x    = (const float*)d_in[0];
    const float* W    = (const float*)d_in[1];
    const float* U    = (const float*)d_in[2];
    const float* bias = (const float*)d_in[3];
    // d_in[4] = seq_len: reference ignores it
    float* out = (float*)d_out;

    split_x_kernel<<<(BATCH * TSTEPS * DDIM / 4) / 256, 256>>>(x);

    cudaFuncSetAttribute(lstm_main_kernel,
                         cudaFuncAttributeMaxDynamicSharedMemorySize, SMEM_MAIN);
    lstm_main_kernel<<<128, THREADS, SMEM_MAIN>>>(W, U, bias, out);
}